// round 9
// baseline (speedup 1.0000x reference)
#include <cuda_runtime.h>

#define N_NODES 200000
#define C 256
#define VC 16
#define VD 3
#define M_SEG 50000

// float4 counts for the mean buffer: [s_mean | v_mean]
#define S_SUM_F4 (M_SEG * (C / 4))            // 3,200,000
#define V_SUM_F4 (M_SEG * (VC * VD / 4))      // 600,000
#define TOT_F4   (S_SUM_F4 + V_SUM_F4)

__device__ float4 g_acc[TOT_F4];              // s_mean / v_mean (written by gather, no zero needed)
__device__ int    g_cnt[M_SEG];
__device__ int    g_incl[M_SEG];
__device__ int    g_offs[M_SEG];
__device__ int    g_run[M_SEG];
__device__ int    g_bsum[128];
__device__ int    g_bpre[128];
__device__ int    g_perm[N_NODES];
__device__ int    g_seg_is64;

#define SCAN_B 512
#define SCAN_NB ((M_SEG + SCAN_B - 1) / SCAN_B)   // 98

// ---------------------------------------------------------------------------
// f32x2 packed-FMA helpers (sm_100+; ptxas never auto-fuses, PTX-only)
// ---------------------------------------------------------------------------
__device__ __forceinline__ unsigned long long ffma2(unsigned long long a,
                                                    unsigned long long b,
                                                    unsigned long long c) {
    unsigned long long d;
    asm("fma.rn.f32x2 %0, %1, %2, %3;" : "=l"(d) : "l"(a), "l"(b), "l"(c));
    return d;
}

__device__ __forceinline__ unsigned long long pack_dup(float x) {
    unsigned long long r;
    unsigned int b = __float_as_uint(x);
    asm("mov.b64 %0, {%1, %1};" : "=l"(r) : "r"(b));
    return r;
}

__device__ __forceinline__ void unpack2(unsigned long long p, float& lo, float& hi) {
    lo = __uint_as_float((unsigned int)p);
    hi = __uint_as_float((unsigned int)(p >> 32));
}

// ---------------------------------------------------------------------------
// Detect whether motif_batch is int64 or int32 (JAX may silently downcast).
// ---------------------------------------------------------------------------
__global__ void detect_k(const unsigned long long* __restrict__ p) {
    if (threadIdx.x == 0 && blockIdx.x == 0) {
        int is64 = 1;
        #pragma unroll
        for (int i = 0; i < 16; i++) {
            if ((p[i] >> 32) != 0ULL) { is64 = 0; }
        }
        g_seg_is64 = is64;
    }
}

__device__ __forceinline__ int get_seg(const void* segp, int node, int is64) {
    if (is64) return (int)((const long long*)segp)[node];
    return ((const int*)segp)[node];
}

// ---------------------------------------------------------------------------
// Counting sort: histogram -> scan -> permutation
// ---------------------------------------------------------------------------
__global__ void zero_cnt_k() {
    int i = blockIdx.x * blockDim.x + threadIdx.x;
    if (i < M_SEG) g_cnt[i] = 0;
}

__global__ void hist_k(const void* __restrict__ segp) {
    int i = blockIdx.x * blockDim.x + threadIdx.x;
    if (i < N_NODES) {
        int m = get_seg(segp, i, g_seg_is64);
        atomicAdd(&g_cnt[m], 1);
    }
}

__global__ void scan1_k() {
    __shared__ int sm[SCAN_B];
    int t = threadIdx.x;
    int i = blockIdx.x * SCAN_B + t;
    int x = (i < M_SEG) ? g_cnt[i] : 0;
    sm[t] = x;
    __syncthreads();
    #pragma unroll
    for (int off = 1; off < SCAN_B; off <<= 1) {
        int y = (t >= off) ? sm[t - off] : 0;
        __syncthreads();
        sm[t] += y;
        __syncthreads();
    }
    if (i < M_SEG) g_incl[i] = sm[t];
    if (t == SCAN_B - 1) g_bsum[blockIdx.x] = sm[t];
}

__global__ void scan2_k() {
    __shared__ int sm[128];
    int t = threadIdx.x;
    int x = (t < SCAN_NB) ? g_bsum[t] : 0;
    sm[t] = x;
    __syncthreads();
    #pragma unroll
    for (int off = 1; off < 128; off <<= 1) {
        int y = (t >= off) ? sm[t - off] : 0;
        __syncthreads();
        sm[t] += y;
        __syncthreads();
    }
    if (t < SCAN_NB) g_bpre[t] = sm[t] - x;   // exclusive
}

__global__ void scan3_k() {
    int i = blockIdx.x * blockDim.x + threadIdx.x;
    if (i < M_SEG) {
        int off = g_incl[i] - g_cnt[i] + g_bpre[i / SCAN_B];
        g_offs[i] = off;
        g_run[i]  = off;
    }
}

__global__ void permute_k(const void* __restrict__ segp) {
    int i = blockIdx.x * blockDim.x + threadIdx.x;
    if (i < N_NODES) {
        int m = get_seg(segp, i, g_seg_is64);
        int pos = atomicAdd(&g_run[m], 1);
        g_perm[pos] = i;
    }
}

// ---------------------------------------------------------------------------
// Gather: one warp per segment, coalesced row loads, writes MEANS directly.
// ---------------------------------------------------------------------------
__global__ void __launch_bounds__(256) gather_k(const float4* __restrict__ s4,
                                                const float4* __restrict__ v4) {
    int w    = (blockIdx.x * blockDim.x + threadIdx.x) >> 5;
    int lane = threadIdx.x & 31;
    if (w >= M_SEG) return;

    int start = g_offs[w];
    int cnt   = g_cnt[w];

    float4 sa0 = make_float4(0.f, 0.f, 0.f, 0.f);
    float4 sa1 = make_float4(0.f, 0.f, 0.f, 0.f);
    float4 va  = make_float4(0.f, 0.f, 0.f, 0.f);

    for (int base = 0; base < cnt; base += 32) {
        int nchunk = min(32, cnt - base);
        int node_l = (lane < nchunk) ? g_perm[start + base + lane] : 0;
        for (int j = 0; j < nchunk; j++) {
            int node = __shfl_sync(0xffffffffu, node_l, j);
            const float4* sr = s4 + (size_t)node * 64;
            float4 a = sr[lane];
            float4 b = sr[32 + lane];
            sa0.x += a.x; sa0.y += a.y; sa0.z += a.z; sa0.w += a.w;
            sa1.x += b.x; sa1.y += b.y; sa1.z += b.z; sa1.w += b.w;
            if (lane < 12) {
                float4 c = v4[(size_t)node * 12 + lane];
                va.x += c.x; va.y += c.y; va.z += c.z; va.w += c.w;
            }
        }
    }

    float inv = 1.0f / (float)max(cnt, 1);
    float4* so = &g_acc[(size_t)w * 64];
    so[lane]      = make_float4(sa0.x * inv, sa0.y * inv, sa0.z * inv, sa0.w * inv);
    so[32 + lane] = make_float4(sa1.x * inv, sa1.y * inv, sa1.z * inv, sa1.w * inv);
    if (lane < 12) {
        g_acc[S_SUM_F4 + (size_t)w * 12 + lane] =
            make_float4(va.x * inv, va.y * inv, va.z * inv, va.w * inv);
    }
}

// ---------------------------------------------------------------------------
// s_out = s_mean @ Ws^T + bs     [50000, 256] x [256, 256]
// 256x64x16 tiles, 256 threads, 16Mx4N micro-tile, f32x2-packed accumulators.
// ---------------------------------------------------------------------------
#define BM 256
#define BN 64
#define BK 16
#define BS_PAD 68

__global__ void __launch_bounds__(256, 2) finish_s_k(const float* __restrict__ Ws,
                                                     const float* __restrict__ bs,
                                                     float* __restrict__ out) {
    __shared__ float As[BK * BM];        // As[k][m], m contiguous
    __shared__ float Bs[BK * BS_PAD];    // Bs[k][n], n contiguous (padded)

    int t  = threadIdx.x;
    int m0 = blockIdx.x * BM;
    int n0 = blockIdx.y * BN;
    int tx = t & 15;
    int ty = t >> 4;
    int bn = t >> 2;
    int bk = t & 3;

    const float4* A4 = (const float4*)g_acc;   // s_mean at offset 0
    const float4* W4 = (const float4*)Ws;

    int ar = m0 + t;

    unsigned long long acc[8][4];
    #pragma unroll
    for (int i = 0; i < 8; i++)
        #pragma unroll
        for (int j = 0; j < 4; j++) acc[i][j] = 0ULL;

    for (int k0 = 0; k0 < C; k0 += BK) {
        float4 av[4];
        #pragma unroll
        for (int q = 0; q < 4; q++) {
            av[q] = (ar < M_SEG) ? A4[(size_t)ar * (C / 4) + (k0 >> 2) + q]
                                 : make_float4(0.f, 0.f, 0.f, 0.f);
        }
        float4 wv = W4[(size_t)(n0 + bn) * (C / 4) + (k0 >> 2) + bk];

        __syncthreads();

        #pragma unroll
        for (int q = 0; q < 4; q++) {
            As[(q * 4 + 0) * BM + t] = av[q].x;
            As[(q * 4 + 1) * BM + t] = av[q].y;
            As[(q * 4 + 2) * BM + t] = av[q].z;
            As[(q * 4 + 3) * BM + t] = av[q].w;
        }
        Bs[(bk * 4 + 0) * BS_PAD + bn] = wv.x;
        Bs[(bk * 4 + 1) * BS_PAD + bn] = wv.y;
        Bs[(bk * 4 + 2) * BS_PAD + bn] = wv.z;
        Bs[(bk * 4 + 3) * BS_PAD + bn] = wv.w;
        __syncthreads();

        #pragma unroll
        for (int kk = 0; kk < BK; kk++) {
            const ulonglong2* ap = (const ulonglong2*)&As[kk * BM + ty * 16];
            ulonglong2 p0 = ap[0], p1 = ap[1], p2 = ap[2], p3 = ap[3];
            unsigned long long a[8] = {p0.x, p0.y, p1.x, p1.y,
                                       p2.x, p2.y, p3.x, p3.y};
            float4 bv = *(const float4*)&Bs[kk * BS_PAD + tx * 4];
            unsigned long long bd[4] = {pack_dup(bv.x), pack_dup(bv.y),
                                        pack_dup(bv.z), pack_dup(bv.w)};
            #pragma unroll
            for (int i = 0; i < 8; i++)
                #pragma unroll
                for (int j = 0; j < 4; j++)
                    acc[i][j] = ffma2(a[i], bd[j], acc[i][j]);
        }
    }

    float4 bsv = *(const float4*)&bs[n0 + tx * 4];
    #pragma unroll
    for (int i = 0; i < 8; i++) {
        int r0 = m0 + ty * 16 + 2 * i;
        float lo0, hi0, lo1, hi1, lo2, hi2, lo3, hi3;
        unpack2(acc[i][0], lo0, hi0);
        unpack2(acc[i][1], lo1, hi1);
        unpack2(acc[i][2], lo2, hi2);
        unpack2(acc[i][3], lo3, hi3);
        if (r0 < M_SEG) {
            float4 o = make_float4(lo0 + bsv.x, lo1 + bsv.y,
                                   lo2 + bsv.z, lo3 + bsv.w);
            *(float4*)&out[(size_t)r0 * C + n0 + tx * 4] = o;
        }
        if (r0 + 1 < M_SEG) {
            float4 o = make_float4(hi0 + bsv.x, hi1 + bsv.y,
                                   hi2 + bsv.z, hi3 + bsv.w);
            *(float4*)&out[(size_t)(r0 + 1) * C + n0 + tx * 4] = o;
        }
    }
}

// ---------------------------------------------------------------------------
// v_out[m,o,d] = sum_c v_mean[m,c,d] * Wv[o,c] + bv[o]
// ---------------------------------------------------------------------------
__global__ void __launch_bounds__(256) finish_v_k(const float* __restrict__ Wv,
                                                  const float* __restrict__ bv,
                                                  float* __restrict__ vout) {
    __shared__ float vs[16][48];
    __shared__ float wv[16][16];
    __shared__ float bvs[16];

    int tid = threadIdx.x;
    int mbase = blockIdx.x * 16;
    const float* vmean = (const float*)(g_acc + S_SUM_F4);

    for (int i = tid; i < 16 * 48; i += 256) {
        int mi = i / 48, q = i - mi * 48;
        vs[mi][q] = vmean[(size_t)(mbase + mi) * 48 + q];
    }
    wv[tid >> 4][tid & 15] = Wv[tid];
    if (tid < 16) bvs[tid] = bv[tid];
    __syncthreads();

    int mi = tid >> 4;
    int o  = tid & 15;
    float a0 = 0.f, a1 = 0.f, a2 = 0.f;
    #pragma unroll
    for (int c = 0; c < 16; c++) {
        float w = wv[o][c];
        a0 += vs[mi][c * 3 + 0] * w;
        a1 += vs[mi][c * 3 + 1] * w;
        a2 += vs[mi][c * 3 + 2] * w;
    }
    int m = mbase + mi;
    float b = bvs[o];
    size_t base = (size_t)m * 48 + o * 3;
    vout[base + 0] = a0 + b;
    vout[base + 1] = a1 + b;
    vout[base + 2] = a2 + b;
}

// ---------------------------------------------------------------------------
extern "C" void kernel_launch(void* const* d_in, const int* in_sizes, int n_in,
                              void* d_out, int out_size) {
    const float4* s4  = (const float4*)d_in[0];
    const float4* v4  = (const float4*)d_in[1];
    const void*   seg = d_in[2];
    const float*  Ws  = (const float*)d_in[3];
    const float*  bs  = (const float*)d_in[4];
    const float*  Wv  = (const float*)d_in[5];
    const float*  bv  = (const float*)d_in[6];

    float* out   = (float*)d_out;
    float* s_out = out;
    float* v_out = out + (size_t)M_SEG * C;

    detect_k<<<1, 32>>>((const unsigned long long*)seg);
    zero_cnt_k<<<(M_SEG + 255) / 256, 256>>>();
    hist_k<<<(N_NODES + 255) / 256, 256>>>(seg);
    scan1_k<<<SCAN_NB, SCAN_B>>>();
    scan2_k<<<1, 128>>>();
    scan3_k<<<(M_SEG + 255) / 256, 256>>>();
    permute_k<<<(N_NODES + 255) / 256, 256>>>(seg);
    gather_k<<<(M_SEG * 32 + 255) / 256, 256>>>(s4, v4);

    dim3 gs((M_SEG + BM - 1) / BM, C / BN);
    finish_s_k<<<gs, 256>>>(Ws, bs, s_out);
    finish_v_k<<<M_SEG / 16, 256>>>(Wv, bv, v_out);
}

// round 12
// speedup vs baseline: 1.5043x; 1.5043x over previous
#include <cuda_runtime.h>
#include <cuda_bf16.h>
#include <cstdint>

#define N_NODES 200000
#define C 256
#define VC 16
#define VD 3
#define M_SEG 50000

// float4 counts: [s_sum | v_sum | cnt]
#define S_SUM_F4 (M_SEG * (C / 4))            // 3,200,000
#define V_SUM_F4 (M_SEG * (VC * VD / 4))      // 600,000
#define CNT_F4   (M_SEG / 4)                  // 12,500
#define TOT_F4   (S_SUM_F4 + V_SUM_F4 + CNT_F4)

__device__ float4        g_acc[TOT_F4];       // 61 MB, L2-resident for RED
__device__ float         g_inv_cnt[M_SEG];
__device__ int           g_seg_is64;
__device__ __nv_bfloat16 g_whi[C * C];        // Ws split hi, [n][k] row-major
__device__ __nv_bfloat16 g_wlo[C * C];        // Ws split lo

// ---------------------------------------------------------------------------
// Detect whether motif_batch is int64 or int32 (JAX may silently downcast).
// ---------------------------------------------------------------------------
__global__ void detect_k(const unsigned long long* __restrict__ p) {
    if (threadIdx.x == 0 && blockIdx.x == 0) {
        int is64 = 1;
        #pragma unroll
        for (int i = 0; i < 16; i++) {
            if ((p[i] >> 32) != 0ULL) { is64 = 0; }
        }
        g_seg_is64 = is64;
    }
}

__global__ void zero_k() {
    int idx = blockIdx.x * blockDim.x + threadIdx.x;
    if (idx < TOT_F4) g_acc[idx] = make_float4(0.f, 0.f, 0.f, 0.f);
}

__device__ __forceinline__ int get_seg(const void* segp, int node, int is64) {
    if (is64) return (int)((const long long*)segp)[node];
    return ((const int*)segp)[node];
}

__device__ __forceinline__ void red_add_v4(float* p, float4 v) {
    asm volatile("red.global.add.v4.f32 [%0], {%1,%2,%3,%4};"
                 :: "l"(p), "f"(v.x), "f"(v.y), "f"(v.z), "f"(v.w) : "memory");
}

__device__ __forceinline__ void red_add_f32(float* p, float v) {
    asm volatile("red.global.add.f32 [%0], %1;" :: "l"(p), "f"(v) : "memory");
}

__global__ void scatter_k(const float4* __restrict__ s4,
                          const float4* __restrict__ v4,
                          const void*   __restrict__ segp) {
    int idx = blockIdx.x * blockDim.x + threadIdx.x;
    int is64 = g_seg_is64;

    if (idx < N_NODES * (C / 4)) {
        int node = idx >> 6;
        int q    = idx & 63;
        int m    = get_seg(segp, node, is64);
        float4 val = s4[idx];
        red_add_v4((float*)&g_acc[m * 64 + q], val);
    }
    if (idx < N_NODES * (VC * VD / 4)) {
        int node = idx / 12;
        int q    = idx - node * 12;
        int m    = get_seg(segp, node, is64);
        float4 val = v4[idx];
        red_add_v4((float*)&g_acc[S_SUM_F4 + m * 12 + q], val);
    }
    if (idx < N_NODES) {
        int m = get_seg(segp, idx, is64);
        float* cnt = (float*)&g_acc[S_SUM_F4 + V_SUM_F4];
        red_add_f32(cnt + m, 1.0f);
    }
}

__global__ void inv_k() {
    int idx = blockIdx.x * blockDim.x + threadIdx.x;
    if (idx < M_SEG) {
        const float* cnt = (const float*)&g_acc[S_SUM_F4 + V_SUM_F4];
        g_inv_cnt[idx] = 1.0f / fmaxf(cnt[idx], 1.0f);
    }
}

// ---------------------------------------------------------------------------
// Split Ws (fp32, [out][in] row-major) into bf16 hi + lo.
// ---------------------------------------------------------------------------
__global__ void prep_w_k(const float* __restrict__ Ws) {
    int i = blockIdx.x * blockDim.x + threadIdx.x;
    if (i < C * C) {
        float w = Ws[i];
        __nv_bfloat16 h = __float2bfloat16(w);
        float hf = __bfloat162float(h);
        g_whi[i] = h;
        g_wlo[i] = __float2bfloat16(w - hf);
    }
}

// ---------------------------------------------------------------------------
// mma.sync helpers (baseline PTX, compiles for compute_103 -> HMMA fallback)
// ---------------------------------------------------------------------------
__device__ __forceinline__ uint32_t smem_u32(const void* p) {
    uint32_t a;
    asm("{ .reg .u64 t; cvta.to.shared.u64 t, %1; cvt.u32.u64 %0, t; }"
        : "=r"(a) : "l"(p));
    return a;
}

#define LDMATRIX_X4(r0, r1, r2, r3, addr) \
    asm volatile("ldmatrix.sync.aligned.m8n8.x4.shared.b16 {%0,%1,%2,%3}, [%4];" \
                 : "=r"(r0), "=r"(r1), "=r"(r2), "=r"(r3) : "r"(addr))

#define LDMATRIX_X2(r0, r1, addr) \
    asm volatile("ldmatrix.sync.aligned.m8n8.x2.shared.b16 {%0,%1}, [%2];" \
                 : "=r"(r0), "=r"(r1) : "r"(addr))

#define MMA_BF16(c, a, b) \
    asm volatile("mma.sync.aligned.m16n8k16.row.col.f32.bf16.bf16.f32 " \
                 "{%0,%1,%2,%3}, {%4,%5,%6,%7}, {%8,%9}, {%0,%1,%2,%3};" \
                 : "+f"((c)[0]), "+f"((c)[1]), "+f"((c)[2]), "+f"((c)[3]) \
                 : "r"((a)[0]), "r"((a)[1]), "r"((a)[2]), "r"((a)[3]), \
                   "r"((b)[0]), "r"((b)[1]))

// ---------------------------------------------------------------------------
// s_out = (s_sum*inv) @ Ws^T + bs via bf16-split mma.sync (3 products).
// CTA 128M x 128N, 8 warps (2M x 4N), warp tile 64M x 32N, K chunks of 32.
// Smem pitch 40 bf16 (80 B): ldmatrix row segments hit disjoint bank quads.
// ---------------------------------------------------------------------------
#define AP 40

__global__ void __launch_bounds__(256) finish_s_mma(const float* __restrict__ bs,
                                                    float* __restrict__ out) {
    __shared__ __nv_bfloat16 Ah[128 * AP];
    __shared__ __nv_bfloat16 Al[128 * AP];
    __shared__ __nv_bfloat16 Bh[128 * AP];
    __shared__ __nv_bfloat16 Bl[128 * AP];

    int tid  = threadIdx.x;
    int wid  = tid >> 5, lane = tid & 31;
    int m0   = blockIdx.x * 128;
    int n0   = blockIdx.y * 128;
    int wm   = (wid >> 2) * 64;     // warp M offset within CTA
    int wn   = (wid & 3) * 32;      // warp N offset within CTA

    // loader role: each thread stages one row-half (16 k) per array
    int lr = tid >> 1;              // 0..127
    int lk = (tid & 1) * 16;        // k offset within 32-wide chunk

    int   arow = m0 + lr;
    float inv  = (arow < M_SEG) ? g_inv_cnt[arow] : 0.f;
    const float4* A4 = (const float4*)g_acc;

    float acc[4][4][4];
    #pragma unroll
    for (int i = 0; i < 4; i++)
        #pragma unroll
        for (int j = 0; j < 4; j++)
            #pragma unroll
            for (int q = 0; q < 4; q++) acc[i][j][q] = 0.f;

    // ldmatrix lane addresses (fixed per thread)
    uint32_t a_base_h = smem_u32(Ah), a_base_l = smem_u32(Al);
    uint32_t b_base_h = smem_u32(Bh), b_base_l = smem_u32(Bl);
    int a_r = wm + (lane & 15);          // + mi*16
    int a_c = (lane >> 4) * 8;           // + k16*16
    int b_r = wn + (lane & 7);           // + ni*8
    int b_c = ((lane >> 3) & 1) * 8;     // + k16*16

    for (int ch = 0; ch < 8; ch++) {
        // ---- stage A: fp32 sums -> *inv -> bf16 hi/lo ----
        {
            const float4* Ag = A4 + (size_t)arow * 64 + ch * 8 + (tid & 1) * 4;
            uint32_t* ah = (uint32_t*)&Ah[lr * AP + lk];
            uint32_t* al = (uint32_t*)&Al[lr * AP + lk];
            #pragma unroll
            for (int q = 0; q < 4; q++) {
                float4 a = (arow < M_SEG) ? Ag[q]
                                          : make_float4(0.f, 0.f, 0.f, 0.f);
                a.x *= inv; a.y *= inv; a.z *= inv; a.w *= inv;
                __nv_bfloat162 h0 = __float22bfloat162_rn(make_float2(a.x, a.y));
                __nv_bfloat162 h1 = __float22bfloat162_rn(make_float2(a.z, a.w));
                __nv_bfloat162 e0 = __float22bfloat162_rn(make_float2(
                    a.x - __low2float(h0), a.y - __high2float(h0)));
                __nv_bfloat162 e1 = __float22bfloat162_rn(make_float2(
                    a.z - __low2float(h1), a.w - __high2float(h1)));
                ah[2 * q]     = *(uint32_t*)&h0;
                ah[2 * q + 1] = *(uint32_t*)&h1;
                al[2 * q]     = *(uint32_t*)&e0;
                al[2 * q + 1] = *(uint32_t*)&e1;
            }
        }
        // ---- stage B: bf16 hi/lo weights, rows n0+lr ----
        {
            const uint4* wh = (const uint4*)(g_whi + (size_t)(n0 + lr) * C + ch * 32 + lk);
            const uint4* wl = (const uint4*)(g_wlo + (size_t)(n0 + lr) * C + ch * 32 + lk);
            uint4 h0 = wh[0], h1 = wh[1];
            uint4 l0 = wl[0], l1 = wl[1];
            uint4* dh = (uint4*)&Bh[lr * AP + lk];
            uint4* dl = (uint4*)&Bl[lr * AP + lk];
            dh[0] = h0; dh[1] = h1;
            dl[0] = l0; dl[1] = l1;
        }
        __syncthreads();

        #pragma unroll
        for (int k16 = 0; k16 < 2; k16++) {
            int kof = k16 * 16;
            uint32_t ah[4][4], al[4][4], bh[4][2], bl[4][2];
            #pragma unroll
            for (int mi = 0; mi < 4; mi++) {
                uint32_t addr = (uint32_t)(((a_r + mi * 16) * AP + kof + a_c) * 2);
                LDMATRIX_X4(ah[mi][0], ah[mi][1], ah[mi][2], ah[mi][3], a_base_h + addr);
                LDMATRIX_X4(al[mi][0], al[mi][1], al[mi][2], al[mi][3], a_base_l + addr);
            }
            #pragma unroll
            for (int ni = 0; ni < 4; ni++) {
                uint32_t addr = (uint32_t)(((b_r + ni * 8) * AP + kof + b_c) * 2);
                LDMATRIX_X2(bh[ni][0], bh[ni][1], b_base_h + addr);
                LDMATRIX_X2(bl[ni][0], bl[ni][1], b_base_l + addr);
            }
            #pragma unroll
            for (int mi = 0; mi < 4; mi++)
                #pragma unroll
                for (int ni = 0; ni < 4; ni++) {
                    MMA_BF16(acc[mi][ni], ah[mi], bh[ni]);
                    MMA_BF16(acc[mi][ni], ah[mi], bl[ni]);
                    MMA_BF16(acc[mi][ni], al[mi], bh[ni]);
                }
        }
        __syncthreads();
    }

    // ---- epilogue: add bias, write ----
    #pragma unroll
    for (int ni = 0; ni < 4; ni++) {
        int col = n0 + wn + ni * 8 + (lane & 3) * 2;
        float2 bb = *(const float2*)&bs[col];
        #pragma unroll
        for (int mi = 0; mi < 4; mi++) {
            int r0 = m0 + wm + mi * 16 + (lane >> 2);
            if (r0 < M_SEG) {
                float2 o = make_float2(acc[mi][ni][0] + bb.x,
                                       acc[mi][ni][1] + bb.y);
                *(float2*)&out[(size_t)r0 * C + col] = o;
            }
            if (r0 + 8 < M_SEG) {
                float2 o = make_float2(acc[mi][ni][2] + bb.x,
                                       acc[mi][ni][3] + bb.y);
                *(float2*)&out[(size_t)(r0 + 8) * C + col] = o;
            }
        }
    }
}

// ---------------------------------------------------------------------------
// v_out[m,o,d] = inv_cnt[m] * sum_c v_sum[m,c,d] * Wv[o,c] + bv[o]
// ---------------------------------------------------------------------------
__global__ void __launch_bounds__(256) finish_v_k(const float* __restrict__ Wv,
                                                  const float* __restrict__ bv,
                                                  float* __restrict__ vout) {
    __shared__ float vs[16][48];
    __shared__ float wv[16][16];
    __shared__ float bvs[16];
    __shared__ float invs[16];

    int tid = threadIdx.x;
    int mbase = blockIdx.x * 16;
    const float* vsum = (const float*)(g_acc + S_SUM_F4);

    for (int i = tid; i < 16 * 48; i += 256) {
        int mi = i / 48, q = i - mi * 48;
        vs[mi][q] = vsum[(size_t)(mbase + mi) * 48 + q];
    }
    wv[tid >> 4][tid & 15] = Wv[tid];
    if (tid < 16) {
        bvs[tid]  = bv[tid];
        invs[tid] = g_inv_cnt[mbase + tid];
    }
    __syncthreads();

    int mi = tid >> 4;
    int o  = tid & 15;
    float a0 = 0.f, a1 = 0.f, a2 = 0.f;
    #pragma unroll
    for (int c = 0; c < 16; c++) {
        float w = wv[o][c];
        a0 += vs[mi][c * 3 + 0] * w;
        a1 += vs[mi][c * 3 + 1] * w;
        a2 += vs[mi][c * 3 + 2] * w;
    }
    int mm = mbase + mi;
    float inv = invs[mi];
    float b = bvs[o];
    size_t base = (size_t)mm * 48 + o * 3;
    vout[base + 0] = a0 * inv + b;
    vout[base + 1] = a1 * inv + b;
    vout[base + 2] = a2 * inv + b;
}

// ---------------------------------------------------------------------------
extern "C" void kernel_launch(void* const* d_in, const int* in_sizes, int n_in,
                              void* d_out, int out_size) {
    const float4* s4  = (const float4*)d_in[0];
    const float4* v4  = (const float4*)d_in[1];
    const void*   seg = d_in[2];
    const float*  Ws  = (const float*)d_in[3];
    const float*  bs  = (const float*)d_in[4];
    const float*  Wv  = (const float*)d_in[5];
    const float*  bv  = (const float*)d_in[6];

    float* out   = (float*)d_out;
    float* s_out = out;
    float* v_out = out + (size_t)M_SEG * C;

    detect_k<<<1, 32>>>((const unsigned long long*)seg);
    zero_k<<<(TOT_F4 + 255) / 256, 256>>>();
    scatter_k<<<(N_NODES * (C / 4) + 255) / 256, 256>>>(s4, v4, seg);
    inv_k<<<(M_SEG + 255) / 256, 256>>>();
    prep_w_k<<<(C * C + 255) / 256, 256>>>(Ws);

    dim3 gs((M_SEG + 127) / 128, C / 128);
    finish_s_mma<<<gs, 256>>>(bs, s_out);
    finish_v_k<<<M_SEG / 16, 256>>>(Wv, bv, v_out);
}

// round 13
// speedup vs baseline: 1.5426x; 1.0254x over previous
#include <cuda_runtime.h>
#include <cuda_bf16.h>
#include <cstdint>

#define N_NODES 200000
#define C 256
#define VC 16
#define VD 3
#define M_SEG 50000

// float4 counts: [s_sum | v_sum | cnt]
#define S_SUM_F4 (M_SEG * (C / 4))            // 3,200,000
#define V_SUM_F4 (M_SEG * (VC * VD / 4))      // 600,000
#define CNT_F4   (M_SEG / 4)                  // 12,500
#define TOT_F4   (S_SUM_F4 + V_SUM_F4 + CNT_F4)

__device__ float4        g_acc[TOT_F4];       // 61 MB, L2-resident for RED
__device__ int           g_seg_is64;
__device__ __nv_bfloat16 g_whi[C * C];        // Ws split hi, [n][k] row-major
__device__ __nv_bfloat16 g_wlo[C * C];        // Ws split lo

// ---------------------------------------------------------------------------
// Fused zero + int64/int32 detection (JAX may silently downcast motif_batch).
// ---------------------------------------------------------------------------
__global__ void zero_detect_k(const unsigned long long* __restrict__ p) {
    int idx = blockIdx.x * blockDim.x + threadIdx.x;
    if (idx < TOT_F4) g_acc[idx] = make_float4(0.f, 0.f, 0.f, 0.f);
    if (blockIdx.x == 0 && threadIdx.x == 0) {
        int is64 = 1;
        #pragma unroll
        for (int i = 0; i < 16; i++) {
            if ((p[i] >> 32) != 0ULL) { is64 = 0; }
        }
        g_seg_is64 = is64;
    }
}

__device__ __forceinline__ int get_seg(const void* segp, int node, int is64) {
    if (is64) return (int)((const long long*)segp)[node];
    return ((const int*)segp)[node];
}

__device__ __forceinline__ void red_add_v4(float* p, float4 v) {
    asm volatile("red.global.add.v4.f32 [%0], {%1,%2,%3,%4};"
                 :: "l"(p), "f"(v.x), "f"(v.y), "f"(v.z), "f"(v.w) : "memory");
}

__device__ __forceinline__ void red_add_f32(float* p, float v) {
    asm volatile("red.global.add.f32 [%0], %1;" :: "l"(p), "f"(v) : "memory");
}

__global__ void scatter_k(const float4* __restrict__ s4,
                          const float4* __restrict__ v4,
                          const void*   __restrict__ segp) {
    int idx = blockIdx.x * blockDim.x + threadIdx.x;
    int is64 = g_seg_is64;

    if (idx < N_NODES * (C / 4)) {
        int node = idx >> 6;
        int q    = idx & 63;
        int m    = get_seg(segp, node, is64);
        float4 val = s4[idx];
        red_add_v4((float*)&g_acc[m * 64 + q], val);
    }
    if (idx < N_NODES * (VC * VD / 4)) {
        int node = idx / 12;
        int q    = idx - node * 12;
        int m    = get_seg(segp, node, is64);
        float4 val = v4[idx];
        red_add_v4((float*)&g_acc[S_SUM_F4 + m * 12 + q], val);
    }
    if (idx < N_NODES) {
        int m = get_seg(segp, idx, is64);
        float* cnt = (float*)&g_acc[S_SUM_F4 + V_SUM_F4];
        red_add_f32(cnt + m, 1.0f);
    }
}

// ---------------------------------------------------------------------------
// Split Ws (fp32, [out][in] row-major) into bf16 hi + lo.
// ---------------------------------------------------------------------------
__global__ void prep_w_k(const float* __restrict__ Ws) {
    int i = blockIdx.x * blockDim.x + threadIdx.x;
    if (i < C * C) {
        float w = Ws[i];
        __nv_bfloat16 h = __float2bfloat16(w);
        float hf = __bfloat162float(h);
        g_whi[i] = h;
        g_wlo[i] = __float2bfloat16(w - hf);
    }
}

// ---------------------------------------------------------------------------
// PTX helpers (baseline PTX only — compiles under compute_103)
// ---------------------------------------------------------------------------
__device__ __forceinline__ uint32_t smem_u32(const void* p) {
    uint32_t a;
    asm("{ .reg .u64 t; cvta.to.shared.u64 t, %1; cvt.u32.u64 %0, t; }"
        : "=r"(a) : "l"(p));
    return a;
}

#define LDMATRIX_X4(r0, r1, r2, r3, addr) \
    asm volatile("ldmatrix.sync.aligned.m8n8.x4.shared.b16 {%0,%1,%2,%3}, [%4];" \
                 : "=r"(r0), "=r"(r1), "=r"(r2), "=r"(r3) : "r"(addr))

#define LDMATRIX_X2(r0, r1, addr) \
    asm volatile("ldmatrix.sync.aligned.m8n8.x2.shared.b16 {%0,%1}, [%2];" \
                 : "=r"(r0), "=r"(r1) : "r"(addr))

#define MMA_BF16(c, a, b) \
    asm volatile("mma.sync.aligned.m16n8k16.row.col.f32.bf16.bf16.f32 " \
                 "{%0,%1,%2,%3}, {%4,%5,%6,%7}, {%8,%9}, {%0,%1,%2,%3};" \
                 : "+f"((c)[0]), "+f"((c)[1]), "+f"((c)[2]), "+f"((c)[3]) \
                 : "r"((a)[0]), "r"((a)[1]), "r"((a)[2]), "r"((a)[3]), \
                   "r"((b)[0]), "r"((b)[1]))

#define CP_ASYNC16(dst, src) \
    asm volatile("cp.async.cg.shared.global [%0], [%1], 16;" \
                 :: "r"(dst), "l"(src) : "memory")
#define CP_COMMIT asm volatile("cp.async.commit_group;" ::: "memory")
#define CP_WAIT0  asm volatile("cp.async.wait_group 0;" ::: "memory")

// ---------------------------------------------------------------------------
// s_out = (s_sum/cnt) @ Ws^T + bs via bf16-split mma.sync (3 products).
// CTA 128M x 128N, 8 warps (2M x 4N), K chunks of 32, double-buffered smem,
// ONE __syncthreads per chunk. A prefetched to regs; B via cp.async.
// Smem pitch 40 bf16 (80 B): ldmatrix row segments hit disjoint bank quads.
// ---------------------------------------------------------------------------
#define AP 40
#define BUF_B   40960u               // bytes per buffer (4 arrays x 10240)
#define AH_B(b) ((b) * BUF_B)
#define AL_B(b) ((b) * BUF_B + 10240u)
#define BH_B(b) ((b) * BUF_B + 20480u)
#define BL_B(b) ((b) * BUF_B + 30720u)
#define FS_SMEM (2 * BUF_B)          // 81920 bytes

__global__ void __launch_bounds__(256) finish_s_mma(const float* __restrict__ bs,
                                                    float* __restrict__ out) {
    extern __shared__ __nv_bfloat16 sm[];
    int tid  = threadIdx.x;
    int wid  = tid >> 5, lane = tid & 31;
    int m0   = blockIdx.x * 128;
    int n0   = blockIdx.y * 128;
    int wm   = (wid >> 2) * 64;
    int wn   = (wid & 3) * 32;

    int lr = tid >> 1;              // 0..127 staging row
    int lk = (tid & 1) * 16;        // k offset within 32-wide chunk

    int   arow = m0 + lr;
    const float* cntp = (const float*)(g_acc + S_SUM_F4 + V_SUM_F4);
    float inv = 0.f;
    if (arow < M_SEG) inv = 1.0f / fmaxf(cntp[arow], 1.0f);
    const float4* A4 = (const float4*)g_acc;

    uint32_t smb = smem_u32(sm);
    uint32_t stA = (uint32_t)(lr * AP + lk) * 2;   // staging byte offset in array
    const char* gBh = (const char*)(g_whi + (size_t)(n0 + lr) * C);
    const char* gBl = (const char*)(g_wlo + (size_t)(n0 + lr) * C);

    float acc[4][4][4];
    #pragma unroll
    for (int i = 0; i < 4; i++)
        #pragma unroll
        for (int j = 0; j < 4; j++)
            #pragma unroll
            for (int q = 0; q < 4; q++) acc[i][j][q] = 0.f;

    // ldmatrix lane geometry (same mapping as validated R12 kernel)
    int a_r = wm + (lane & 15);
    int a_c = (lane >> 4) * 8;
    int b_r = wn + (lane & 7);
    int b_c = ((lane >> 3) & 1) * 8;

    float4 av[4];

    // ---- prologue: stage chunk 0 into buffer 0 ----
    {
        const float4* Ag = A4 + (size_t)arow * 64 + (tid & 1) * 4;
        #pragma unroll
        for (int q = 0; q < 4; q++)
            av[q] = (arow < M_SEG) ? Ag[q] : make_float4(0.f, 0.f, 0.f, 0.f);

        uint32_t dh = smb + BH_B(0) + stA;
        uint32_t dl = smb + BL_B(0) + stA;
        const char* sh = gBh + (size_t)lk * 2;
        const char* sl = gBl + (size_t)lk * 2;
        CP_ASYNC16(dh, sh);      CP_ASYNC16(dh + 16, sh + 16);
        CP_ASYNC16(dl, sl);      CP_ASYNC16(dl + 16, sl + 16);
        CP_COMMIT;

        uint32_t* ah = (uint32_t*)((char*)sm + AH_B(0) + stA);
        uint32_t* al = (uint32_t*)((char*)sm + AL_B(0) + stA);
        #pragma unroll
        for (int q = 0; q < 4; q++) {
            float4 a = av[q];
            a.x *= inv; a.y *= inv; a.z *= inv; a.w *= inv;
            __nv_bfloat162 h0 = __float22bfloat162_rn(make_float2(a.x, a.y));
            __nv_bfloat162 h1 = __float22bfloat162_rn(make_float2(a.z, a.w));
            __nv_bfloat162 e0 = __float22bfloat162_rn(make_float2(
                a.x - __low2float(h0), a.y - __high2float(h0)));
            __nv_bfloat162 e1 = __float22bfloat162_rn(make_float2(
                a.z - __low2float(h1), a.w - __high2float(h1)));
            ah[2 * q]     = *(uint32_t*)&h0;
            ah[2 * q + 1] = *(uint32_t*)&h1;
            al[2 * q]     = *(uint32_t*)&e0;
            al[2 * q + 1] = *(uint32_t*)&e1;
        }
        CP_WAIT0;
        __syncthreads();
    }

    #pragma unroll
    for (int ch = 0; ch < 8; ch++) {
        int b = ch & 1;

        // ---- prefetch chunk ch+1 (A regs + B cp.async) while computing ----
        if (ch < 7) {
            const float4* Ag = A4 + (size_t)arow * 64 + (ch + 1) * 8 + (tid & 1) * 4;
            #pragma unroll
            for (int q = 0; q < 4; q++)
                av[q] = (arow < M_SEG) ? Ag[q] : make_float4(0.f, 0.f, 0.f, 0.f);

            int nb = (ch + 1) & 1;
            uint32_t dh = smb + BH_B(nb) + stA;
            uint32_t dl = smb + BL_B(nb) + stA;
            const char* sh = gBh + (size_t)((ch + 1) * 32 + lk) * 2;
            const char* sl = gBl + (size_t)((ch + 1) * 32 + lk) * 2;
            CP_ASYNC16(dh, sh);      CP_ASYNC16(dh + 16, sh + 16);
            CP_ASYNC16(dl, sl);      CP_ASYNC16(dl + 16, sl + 16);
            CP_COMMIT;
        }

        // ---- compute on buffer b ----
        {
            uint32_t abh = smb + AH_B(b);
            uint32_t abl = smb + AL_B(b);
            uint32_t bbh = smb + BH_B(b);
            uint32_t bbl = smb + BL_B(b);
            #pragma unroll
            for (int k16 = 0; k16 < 2; k16++) {
                int kof = k16 * 16;
                uint32_t ah[4][4], al[4][4], bh[4][2], bl[4][2];
                #pragma unroll
                for (int mi = 0; mi < 4; mi++) {
                    uint32_t addr = (uint32_t)(((a_r + mi * 16) * AP + kof + a_c) * 2);
                    LDMATRIX_X4(ah[mi][0], ah[mi][1], ah[mi][2], ah[mi][3], abh + addr);
                    LDMATRIX_X4(al[mi][0], al[mi][1], al[mi][2], al[mi][3], abl + addr);
                }
                #pragma unroll
                for (int ni = 0; ni < 4; ni++) {
                    uint32_t addr = (uint32_t)(((b_r + ni * 8) * AP + kof + b_c) * 2);
                    LDMATRIX_X2(bh[ni][0], bh[ni][1], bbh + addr);
                    LDMATRIX_X2(bl[ni][0], bl[ni][1], bbl + addr);
                }
                #pragma unroll
                for (int mi = 0; mi < 4; mi++)
                    #pragma unroll
                    for (int ni = 0; ni < 4; ni++) {
                        MMA_BF16(acc[mi][ni], ah[mi], bh[ni]);
                        MMA_BF16(acc[mi][ni], ah[mi], bl[ni]);
                        MMA_BF16(acc[mi][ni], al[mi], bh[ni]);
                    }
            }
        }

        // ---- convert prefetched A into next buffer, single barrier ----
        if (ch < 7) {
            int nb = (ch + 1) & 1;
            uint32_t* ah = (uint32_t*)((char*)sm + AH_B(nb) + stA);
            uint32_t* al = (uint32_t*)((char*)sm + AL_B(nb) + stA);
            #pragma unroll
            for (int q = 0; q < 4; q++) {
                float4 a = av[q];
                a.x *= inv; a.y *= inv; a.z *= inv; a.w *= inv;
                __nv_bfloat162 h0 = __float22bfloat162_rn(make_float2(a.x, a.y));
                __nv_bfloat162 h1 = __float22bfloat162_rn(make_float2(a.z, a.w));
                __nv_bfloat162 e0 = __float22bfloat162_rn(make_float2(
                    a.x - __low2float(h0), a.y - __high2float(h0)));
                __nv_bfloat162 e1 = __float22bfloat162_rn(make_float2(
                    a.z - __low2float(h1), a.w - __high2float(h1)));
                ah[2 * q]     = *(uint32_t*)&h0;
                ah[2 * q + 1] = *(uint32_t*)&h1;
                al[2 * q]     = *(uint32_t*)&e0;
                al[2 * q + 1] = *(uint32_t*)&e1;
            }
            CP_WAIT0;
            __syncthreads();
        }
    }

    // ---- epilogue: add bias, write ----
    #pragma unroll
    for (int ni = 0; ni < 4; ni++) {
        int col = n0 + wn + ni * 8 + (lane & 3) * 2;
        float2 bb = *(const float2*)&bs[col];
        #pragma unroll
        for (int mi = 0; mi < 4; mi++) {
            int r0 = m0 + wm + mi * 16 + (lane >> 2);
            if (r0 < M_SEG) {
                float2 o = make_float2(acc[mi][ni][0] + bb.x,
                                       acc[mi][ni][1] + bb.y);
                *(float2*)&out[(size_t)r0 * C + col] = o;
            }
            if (r0 + 8 < M_SEG) {
                float2 o = make_float2(acc[mi][ni][2] + bb.x,
                                       acc[mi][ni][3] + bb.y);
                *(float2*)&out[(size_t)(r0 + 8) * C + col] = o;
            }
        }
    }
}

// ---------------------------------------------------------------------------
// v_out[m,o,d] = (1/cnt_m) * sum_c v_sum[m,c,d] * Wv[o,c] + bv[o]
// ---------------------------------------------------------------------------
__global__ void __launch_bounds__(256) finish_v_k(const float* __restrict__ Wv,
                                                  const float* __restrict__ bv,
                                                  float* __restrict__ vout) {
    __shared__ float vs[16][48];
    __shared__ float wv[16][16];
    __shared__ float bvs[16];
    __shared__ float invs[16];

    int tid = threadIdx.x;
    int mbase = blockIdx.x * 16;
    const float* vsum = (const float*)(g_acc + S_SUM_F4);
    const float* cntp = (const float*)(g_acc + S_SUM_F4 + V_SUM_F4);

    for (int i = tid; i < 16 * 48; i += 256) {
        int mi = i / 48, q = i - mi * 48;
        vs[mi][q] = vsum[(size_t)(mbase + mi) * 48 + q];
    }
    wv[tid >> 4][tid & 15] = Wv[tid];
    if (tid < 16) {
        bvs[tid]  = bv[tid];
        invs[tid] = 1.0f / fmaxf(cntp[mbase + tid], 1.0f);
    }
    __syncthreads();

    int mi = tid >> 4;
    int o  = tid & 15;
    float a0 = 0.f, a1 = 0.f, a2 = 0.f;
    #pragma unroll
    for (int c = 0; c < 16; c++) {
        float w = wv[o][c];
        a0 += vs[mi][c * 3 + 0] * w;
        a1 += vs[mi][c * 3 + 1] * w;
        a2 += vs[mi][c * 3 + 2] * w;
    }
    int mm = mbase + mi;
    float inv = invs[mi];
    float b = bvs[o];
    size_t base = (size_t)mm * 48 + o * 3;
    vout[base + 0] = a0 * inv + b;
    vout[base + 1] = a1 * inv + b;
    vout[base + 2] = a2 * inv + b;
}

// ---------------------------------------------------------------------------
extern "C" void kernel_launch(void* const* d_in, const int* in_sizes, int n_in,
                              void* d_out, int out_size) {
    const float4* s4  = (const float4*)d_in[0];
    const float4* v4  = (const float4*)d_in[1];
    const void*   seg = d_in[2];
    const float*  Ws  = (const float*)d_in[3];
    const float*  bs  = (const float*)d_in[4];
    const float*  Wv  = (const float*)d_in[5];
    const float*  bv  = (const float*)d_in[6];

    float* out   = (float*)d_out;
    float* s_out = out;
    float* v_out = out + (size_t)M_SEG * C;

    static int smem_set = 0;
    if (!smem_set) {
        cudaFuncSetAttribute(finish_s_mma,
                             cudaFuncAttributeMaxDynamicSharedMemorySize, FS_SMEM);
        smem_set = 1;
    }

    // launch order puts finish_s_mma at profile slot 3
    zero_detect_k<<<(TOT_F4 + 255) / 256, 256>>>((const unsigned long long*)seg);
    prep_w_k<<<(C * C + 255) / 256, 256>>>(Ws);
    scatter_k<<<(N_NODES * (C / 4) + 255) / 256, 256>>>(s4, v4, seg);

    dim3 gs((M_SEG + 127) / 128, C / 128);
    finish_s_mma<<<gs, 256, FS_SMEM>>>(bs, s_out);
    finish_v_k<<<M_SEG / 16, 256>>>(Wv, bv, v_out);
}

// round 14
// speedup vs baseline: 1.6945x; 1.0985x over previous
#include <cuda_runtime.h>
#include <cuda_bf16.h>
#include <cstdint>

#define N_NODES 200000
#define C 256
#define VC 16
#define VD 3
#define M_SEG 50000

// float4 counts: [s_sum | v_sum | cnt]
#define S_SUM_F4 (M_SEG * (C / 4))            // 3,200,000
#define V_SUM_F4 (M_SEG * (VC * VD / 4))      // 600,000
#define CNT_F4   (M_SEG / 4)                  // 12,500
#define TOT_F4   (S_SUM_F4 + V_SUM_F4 + CNT_F4)

__device__ float4        g_acc[TOT_F4];       // 61 MB, L2-resident for RED
__device__ int           g_seg_is64;
__device__ __nv_bfloat16 g_whi[C * C];        // Ws split hi, [n][k] row-major
__device__ __nv_bfloat16 g_wlo[C * C];        // Ws split lo

// ---------------------------------------------------------------------------
// Fused zero + int64/int32 detection (JAX may silently downcast motif_batch).
// ---------------------------------------------------------------------------
__global__ void zero_detect_k(const unsigned long long* __restrict__ p) {
    int idx = blockIdx.x * blockDim.x + threadIdx.x;
    if (idx < TOT_F4) g_acc[idx] = make_float4(0.f, 0.f, 0.f, 0.f);
    if (blockIdx.x == 0 && threadIdx.x == 0) {
        int is64 = 1;
        #pragma unroll
        for (int i = 0; i < 16; i++) {
            if ((p[i] >> 32) != 0ULL) { is64 = 0; }
        }
        g_seg_is64 = is64;
    }
}

__device__ __forceinline__ int get_seg(const void* segp, int node, int is64) {
    if (is64) return (int)((const long long*)segp)[node];
    return ((const int*)segp)[node];
}

__device__ __forceinline__ void red_add_v4(float* p, float4 v) {
    asm volatile("red.global.add.v4.f32 [%0], {%1,%2,%3,%4};"
                 :: "l"(p), "f"(v.x), "f"(v.y), "f"(v.z), "f"(v.w) : "memory");
}

__device__ __forceinline__ void red_add_f32(float* p, float v) {
    asm volatile("red.global.add.f32 [%0], %1;" :: "l"(p), "f"(v) : "memory");
}

__global__ void scatter_k(const float4* __restrict__ s4,
                          const float4* __restrict__ v4,
                          const void*   __restrict__ segp) {
    int idx = blockIdx.x * blockDim.x + threadIdx.x;
    int is64 = g_seg_is64;

    if (idx < N_NODES * (C / 4)) {
        int node = idx >> 6;
        int q    = idx & 63;
        int m    = get_seg(segp, node, is64);
        float4 val = s4[idx];
        red_add_v4((float*)&g_acc[m * 64 + q], val);
    }
    if (idx < N_NODES * (VC * VD / 4)) {
        int node = idx / 12;
        int q    = idx - node * 12;
        int m    = get_seg(segp, node, is64);
        float4 val = v4[idx];
        red_add_v4((float*)&g_acc[S_SUM_F4 + m * 12 + q], val);
    }
    if (idx < N_NODES) {
        int m = get_seg(segp, idx, is64);
        float* cnt = (float*)&g_acc[S_SUM_F4 + V_SUM_F4];
        red_add_f32(cnt + m, 1.0f);
    }
}

// ---------------------------------------------------------------------------
// Split Ws (fp32, [out][in] row-major) into bf16 hi + lo.
// ---------------------------------------------------------------------------
__global__ void prep_w_k(const float* __restrict__ Ws) {
    int i = blockIdx.x * blockDim.x + threadIdx.x;
    if (i < C * C) {
        float w = Ws[i];
        __nv_bfloat16 h = __float2bfloat16(w);
        float hf = __bfloat162float(h);
        g_whi[i] = h;
        g_wlo[i] = __float2bfloat16(w - hf);
    }
}

// ---------------------------------------------------------------------------
// PTX helpers (baseline PTX only — compiles under compute_103)
// ---------------------------------------------------------------------------
__device__ __forceinline__ uint32_t smem_u32(const void* p) {
    uint32_t a;
    asm("{ .reg .u64 t; cvta.to.shared.u64 t, %1; cvt.u32.u64 %0, t; }"
        : "=r"(a) : "l"(p));
    return a;
}

#define LDMATRIX_X4(r0, r1, r2, r3, addr) \
    asm volatile("ldmatrix.sync.aligned.m8n8.x4.shared.b16 {%0,%1,%2,%3}, [%4];" \
                 : "=r"(r0), "=r"(r1), "=r"(r2), "=r"(r3) : "r"(addr))

#define LDMATRIX_X2(r0, r1, addr) \
    asm volatile("ldmatrix.sync.aligned.m8n8.x2.shared.b16 {%0,%1}, [%2];" \
                 : "=r"(r0), "=r"(r1) : "r"(addr))

#define MMA_BF16(c, a, b) \
    asm volatile("mma.sync.aligned.m16n8k16.row.col.f32.bf16.bf16.f32 " \
                 "{%0,%1,%2,%3}, {%4,%5,%6,%7}, {%8,%9}, {%0,%1,%2,%3};" \
                 : "+f"((c)[0]), "+f"((c)[1]), "+f"((c)[2]), "+f"((c)[3]) \
                 : "r"((a)[0]), "r"((a)[1]), "r"((a)[2]), "r"((a)[3]), \
                   "r"((b)[0]), "r"((b)[1]))

#define CP_ASYNC16(dst, src) \
    asm volatile("cp.async.cg.shared.global [%0], [%1], 16;" \
                 :: "r"(dst), "l"(src) : "memory")
#define CP_COMMIT asm volatile("cp.async.commit_group;" ::: "memory")
#define CP_WAIT0  asm volatile("cp.async.wait_group 0;" ::: "memory")

// ---------------------------------------------------------------------------
// s_out = (s_sum/cnt) @ Ws^T + bs via bf16-split mma.sync (3 products).
// CTA 128M x 128N, 8 warps (2M x 4N), K chunks of 32, double-buffered smem,
// ONE __syncthreads per chunk. A prefetched to regs; B via cp.async.
// __launch_bounds__(256, 2): cap regs at 128 so 2 CTAs/SM (4 warps/SMSP) —
// R13 profile showed occ=12.5% (1 CTA, regs=140) starving the tensor pipe.
// Smem pitch 40 bf16 (80 B): ldmatrix row segments hit disjoint bank quads.
// ---------------------------------------------------------------------------
#define AP 40
#define BUF_B   40960u               // bytes per buffer (4 arrays x 10240)
#define AH_B(b) ((b) * BUF_B)
#define AL_B(b) ((b) * BUF_B + 10240u)
#define BH_B(b) ((b) * BUF_B + 20480u)
#define BL_B(b) ((b) * BUF_B + 30720u)
#define FS_SMEM (2 * BUF_B)          // 81920 bytes

__global__ void __launch_bounds__(256, 2) finish_s_mma(const float* __restrict__ bs,
                                                       float* __restrict__ out) {
    extern __shared__ __nv_bfloat16 sm[];
    int tid  = threadIdx.x;
    int wid  = tid >> 5, lane = tid & 31;
    int m0   = blockIdx.x * 128;
    int n0   = blockIdx.y * 128;
    int wm   = (wid >> 2) * 64;
    int wn   = (wid & 3) * 32;

    int lr = tid >> 1;              // 0..127 staging row
    int lk = (tid & 1) * 16;        // k offset within 32-wide chunk

    int   arow = m0 + lr;
    const float* cntp = (const float*)(g_acc + S_SUM_F4 + V_SUM_F4);
    float inv = 0.f;
    if (arow < M_SEG) inv = 1.0f / fmaxf(cntp[arow], 1.0f);
    const float4* A4 = (const float4*)g_acc;

    uint32_t smb = smem_u32(sm);
    uint32_t stA = (uint32_t)(lr * AP + lk) * 2;   // staging byte offset in array
    const char* gBh = (const char*)(g_whi + (size_t)(n0 + lr) * C);
    const char* gBl = (const char*)(g_wlo + (size_t)(n0 + lr) * C);

    float acc[4][4][4];
    #pragma unroll
    for (int i = 0; i < 4; i++)
        #pragma unroll
        for (int j = 0; j < 4; j++)
            #pragma unroll
            for (int q = 0; q < 4; q++) acc[i][j][q] = 0.f;

    // ldmatrix lane geometry (same mapping as validated R12 kernel)
    int a_r = wm + (lane & 15);
    int a_c = (lane >> 4) * 8;
    int b_r = wn + (lane & 7);
    int b_c = ((lane >> 3) & 1) * 8;

    float4 av[4];

    // ---- prologue: stage chunk 0 into buffer 0 ----
    {
        const float4* Ag = A4 + (size_t)arow * 64 + (tid & 1) * 4;
        #pragma unroll
        for (int q = 0; q < 4; q++)
            av[q] = (arow < M_SEG) ? Ag[q] : make_float4(0.f, 0.f, 0.f, 0.f);

        uint32_t dh = smb + BH_B(0) + stA;
        uint32_t dl = smb + BL_B(0) + stA;
        const char* sh = gBh + (size_t)lk * 2;
        const char* sl = gBl + (size_t)lk * 2;
        CP_ASYNC16(dh, sh);      CP_ASYNC16(dh + 16, sh + 16);
        CP_ASYNC16(dl, sl);      CP_ASYNC16(dl + 16, sl + 16);
        CP_COMMIT;

        uint32_t* ah = (uint32_t*)((char*)sm + AH_B(0) + stA);
        uint32_t* al = (uint32_t*)((char*)sm + AL_B(0) + stA);
        #pragma unroll
        for (int q = 0; q < 4; q++) {
            float4 a = av[q];
            a.x *= inv; a.y *= inv; a.z *= inv; a.w *= inv;
            __nv_bfloat162 h0 = __float22bfloat162_rn(make_float2(a.x, a.y));
            __nv_bfloat162 h1 = __float22bfloat162_rn(make_float2(a.z, a.w));
            __nv_bfloat162 e0 = __float22bfloat162_rn(make_float2(
                a.x - __low2float(h0), a.y - __high2float(h0)));
            __nv_bfloat162 e1 = __float22bfloat162_rn(make_float2(
                a.z - __low2float(h1), a.w - __high2float(h1)));
            ah[2 * q]     = *(uint32_t*)&h0;
            ah[2 * q + 1] = *(uint32_t*)&h1;
            al[2 * q]     = *(uint32_t*)&e0;
            al[2 * q + 1] = *(uint32_t*)&e1;
        }
        CP_WAIT0;
        __syncthreads();
    }

    #pragma unroll
    for (int ch = 0; ch < 8; ch++) {
        int b = ch & 1;

        // ---- prefetch chunk ch+1 (A regs + B cp.async) while computing ----
        if (ch < 7) {
            const float4* Ag = A4 + (size_t)arow * 64 + (ch + 1) * 8 + (tid & 1) * 4;
            #pragma unroll
            for (int q = 0; q < 4; q++)
                av[q] = (arow < M_SEG) ? Ag[q] : make_float4(0.f, 0.f, 0.f, 0.f);

            int nb = (ch + 1) & 1;
            uint32_t dh = smb + BH_B(nb) + stA;
            uint32_t dl = smb + BL_B(nb) + stA;
            const char* sh = gBh + (size_t)((ch + 1) * 32 + lk) * 2;
            const char* sl = gBl + (size_t)((ch + 1) * 32 + lk) * 2;
            CP_ASYNC16(dh, sh);      CP_ASYNC16(dh + 16, sh + 16);
            CP_ASYNC16(dl, sl);      CP_ASYNC16(dl + 16, sl + 16);
            CP_COMMIT;
        }

        // ---- compute on buffer b ----
        {
            uint32_t abh = smb + AH_B(b);
            uint32_t abl = smb + AL_B(b);
            uint32_t bbh = smb + BH_B(b);
            uint32_t bbl = smb + BL_B(b);
            #pragma unroll
            for (int k16 = 0; k16 < 2; k16++) {
                int kof = k16 * 16;
                uint32_t ah[4][4], al[4][4], bh[4][2], bl[4][2];
                #pragma unroll
                for (int mi = 0; mi < 4; mi++) {
                    uint32_t addr = (uint32_t)(((a_r + mi * 16) * AP + kof + a_c) * 2);
                    LDMATRIX_X4(ah[mi][0], ah[mi][1], ah[mi][2], ah[mi][3], abh + addr);
                    LDMATRIX_X4(al[mi][0], al[mi][1], al[mi][2], al[mi][3], abl + addr);
                }
                #pragma unroll
                for (int ni = 0; ni < 4; ni++) {
                    uint32_t addr = (uint32_t)(((b_r + ni * 8) * AP + kof + b_c) * 2);
                    LDMATRIX_X2(bh[ni][0], bh[ni][1], bbh + addr);
                    LDMATRIX_X2(bl[ni][0], bl[ni][1], bbl + addr);
                }
                #pragma unroll
                for (int mi = 0; mi < 4; mi++)
                    #pragma unroll
                    for (int ni = 0; ni < 4; ni++) {
                        MMA_BF16(acc[mi][ni], ah[mi], bh[ni]);
                        MMA_BF16(acc[mi][ni], ah[mi], bl[ni]);
                        MMA_BF16(acc[mi][ni], al[mi], bh[ni]);
                    }
            }
        }

        // ---- convert prefetched A into next buffer, single barrier ----
        if (ch < 7) {
            int nb = (ch + 1) & 1;
            uint32_t* ah = (uint32_t*)((char*)sm + AH_B(nb) + stA);
            uint32_t* al = (uint32_t*)((char*)sm + AL_B(nb) + stA);
            #pragma unroll
            for (int q = 0; q < 4; q++) {
                float4 a = av[q];
                a.x *= inv; a.y *= inv; a.z *= inv; a.w *= inv;
                __nv_bfloat162 h0 = __float22bfloat162_rn(make_float2(a.x, a.y));
                __nv_bfloat162 h1 = __float22bfloat162_rn(make_float2(a.z, a.w));
                __nv_bfloat162 e0 = __float22bfloat162_rn(make_float2(
                    a.x - __low2float(h0), a.y - __high2float(h0)));
                __nv_bfloat162 e1 = __float22bfloat162_rn(make_float2(
                    a.z - __low2float(h1), a.w - __high2float(h1)));
                ah[2 * q]     = *(uint32_t*)&h0;
                ah[2 * q + 1] = *(uint32_t*)&h1;
                al[2 * q]     = *(uint32_t*)&e0;
                al[2 * q + 1] = *(uint32_t*)&e1;
            }
            CP_WAIT0;
            __syncthreads();
        }
    }

    // ---- epilogue: add bias, write ----
    #pragma unroll
    for (int ni = 0; ni < 4; ni++) {
        int col = n0 + wn + ni * 8 + (lane & 3) * 2;
        float2 bb = *(const float2*)&bs[col];
        #pragma unroll
        for (int mi = 0; mi < 4; mi++) {
            int r0 = m0 + wm + mi * 16 + (lane >> 2);
            if (r0 < M_SEG) {
                float2 o = make_float2(acc[mi][ni][0] + bb.x,
                                       acc[mi][ni][1] + bb.y);
                *(float2*)&out[(size_t)r0 * C + col] = o;
            }
            if (r0 + 8 < M_SEG) {
                float2 o = make_float2(acc[mi][ni][2] + bb.x,
                                       acc[mi][ni][3] + bb.y);
                *(float2*)&out[(size_t)(r0 + 8) * C + col] = o;
            }
        }
    }
}

// ---------------------------------------------------------------------------
// v_out[m,o,d] = (1/cnt_m) * sum_c v_sum[m,c,d] * Wv[o,c] + bv[o]
// ---------------------------------------------------------------------------
__global__ void __launch_bounds__(256) finish_v_k(const float* __restrict__ Wv,
                                                  const float* __restrict__ bv,
                                                  float* __restrict__ vout) {
    __shared__ float vs[16][48];
    __shared__ float wv[16][16];
    __shared__ float bvs[16];
    __shared__ float invs[16];

    int tid = threadIdx.x;
    int mbase = blockIdx.x * 16;
    const float* vsum = (const float*)(g_acc + S_SUM_F4);
    const float* cntp = (const float*)(g_acc + S_SUM_F4 + V_SUM_F4);

    for (int i = tid; i < 16 * 48; i += 256) {
        int mi = i / 48, q = i - mi * 48;
        vs[mi][q] = vsum[(size_t)(mbase + mi) * 48 + q];
    }
    wv[tid >> 4][tid & 15] = Wv[tid];
    if (tid < 16) {
        bvs[tid]  = bv[tid];
        invs[tid] = 1.0f / fmaxf(cntp[mbase + tid], 1.0f);
    }
    __syncthreads();

    int mi = tid >> 4;
    int o  = tid & 15;
    float a0 = 0.f, a1 = 0.f, a2 = 0.f;
    #pragma unroll
    for (int c = 0; c < 16; c++) {
        float w = wv[o][c];
        a0 += vs[mi][c * 3 + 0] * w;
        a1 += vs[mi][c * 3 + 1] * w;
        a2 += vs[mi][c * 3 + 2] * w;
    }
    int mm = mbase + mi;
    float inv = invs[mi];
    float b = bvs[o];
    size_t base = (size_t)mm * 48 + o * 3;
    vout[base + 0] = a0 * inv + b;
    vout[base + 1] = a1 * inv + b;
    vout[base + 2] = a2 * inv + b;
}

// ---------------------------------------------------------------------------
extern "C" void kernel_launch(void* const* d_in, const int* in_sizes, int n_in,
                              void* d_out, int out_size) {
    const float4* s4  = (const float4*)d_in[0];
    const float4* v4  = (const float4*)d_in[1];
    const void*   seg = d_in[2];
    const float*  Ws  = (const float*)d_in[3];
    const float*  bs  = (const float*)d_in[4];
    const float*  Wv  = (const float*)d_in[5];
    const float*  bv  = (const float*)d_in[6];

    float* out   = (float*)d_out;
    float* s_out = out;
    float* v_out = out + (size_t)M_SEG * C;

    static int smem_set = 0;
    if (!smem_set) {
        cudaFuncSetAttribute(finish_s_mma,
                             cudaFuncAttributeMaxDynamicSharedMemorySize, FS_SMEM);
        smem_set = 1;
    }

    // launch order puts finish_s_mma at profile slot 3
    zero_detect_k<<<(TOT_F4 + 255) / 256, 256>>>((const unsigned long long*)seg);
    prep_w_k<<<(C * C + 255) / 256, 256>>>(Ws);
    scatter_k<<<(N_NODES * (C / 4) + 255) / 256, 256>>>(s4, v4, seg);

    dim3 gs((M_SEG + 127) / 128, C / 128);
    finish_s_mma<<<gs, 256, FS_SMEM>>>(bs, s_out);
    finish_v_k<<<M_SEG / 16, 256>>>(Wv, bv, v_out);
}